// round 8
// baseline (speedup 1.0000x reference)
#include <cuda_runtime.h>
#include <cstdint>

// ---------------------------------------------------------------------------
// SABlock: causal MHA block. B=4, T=2048, C=1024, H=16, D=64.
// Round 8: tcgen05 unavailable (harness targets compute_100, no 'a' feature).
// GEMMs = round-6 mma.sync tf32 (proven). Attention rebuilt: 256-row q-tiles,
// 32 rows/warp, P kept in registers via quad-shfl acc->A-frag remap.
// ---------------------------------------------------------------------------

#define BB 4
#define TT 2048
#define CC 1024
#define HH 16
#define DD 64

__device__ __align__(16) float g_Q[BB * HH * TT * DD];
__device__ __align__(16) float g_K[BB * HH * TT * DD];
__device__ __align__(16) float g_V[BB * HH * TT * DD];
__device__ __align__(16) float g_Y[BB * TT * CC];

__device__ __forceinline__ float to_tf32(float x) {
    uint32_t u;
    asm("cvt.rna.tf32.f32 %0, %1;" : "=r"(u) : "f"(x));
    return __uint_as_float(u);
}
__device__ __forceinline__ uint32_t smem_u32(const void* p) {
    return (uint32_t)__cvta_generic_to_shared(p);
}

#define LDSM4(r, addr)                                                        \
    asm volatile("ldmatrix.sync.aligned.m8n8.x4.shared.b16 {%0,%1,%2,%3}, [%4];" \
                 : "=r"((r)[0]), "=r"((r)[1]), "=r"((r)[2]), "=r"((r)[3])     \
                 : "r"(addr))

#define MMA_TF32(c, a, b0_, b1_)                                              \
    asm volatile("mma.sync.aligned.m16n8k8.row.col.f32.tf32.tf32.f32 "        \
                 "{%0,%1,%2,%3},{%4,%5,%6,%7},{%8,%9},{%0,%1,%2,%3};"         \
                 : "+f"((c)[0]), "+f"((c)[1]), "+f"((c)[2]), "+f"((c)[3])     \
                 : "r"((a)[0]), "r"((a)[1]), "r"((a)[2]), "r"((a)[3]),        \
                   "r"(b0_), "r"(b1_))

// ---------------------------------------------------------------------------
// tf32 GEMM core (round 6, unchanged): 128x128 block tile, 4 warps 64x64,
// K-step 16, double-buffered smem.
// ---------------------------------------------------------------------------
__device__ __forceinline__ void gemm_tf32(const float* __restrict__ A,
                                          const float* __restrict__ W,
                                          int m0, int n0, float acc[4][8][4])
{
    __shared__ float As[2][128][20];
    __shared__ float Bs[2][128][20];

    const int t    = threadIdx.x;
    const int lane = t & 31;
    const int wid  = t >> 5;
    const int wm   = (wid & 1) * 64;
    const int wn   = (wid >> 1) * 64;

    const int lr = t >> 2;
    const int lc = (t & 3) * 4;
    const float* Ap = A + (size_t)(m0 + lr) * CC + lc;
    const float* Bp = W + (size_t)(n0 + lr) * CC + lc;

    const int arow = (lane & 7) + ((lane >> 3) & 1) * 8;
    const int akw  = (lane >> 4) * 4;
    const int brow = (lane & 7) + (lane >> 4) * 8;
    const int bkw  = ((lane >> 3) & 1) * 4;

    const uint32_t aBase = smem_u32(&As[0][0][0]) + (((wm + arow) * 20 + akw) << 2);
    const uint32_t bBase = smem_u32(&Bs[0][0][0]) + (((wn + brow) * 20 + bkw) << 2);
    const uint32_t BUFA  = sizeof(float) * 128 * 20;

    #pragma unroll
    for (int i = 0; i < 4; i++)
        #pragma unroll
        for (int nt = 0; nt < 8; nt++)
            #pragma unroll
            for (int c = 0; c < 4; c++) acc[i][nt][c] = 0.f;

    float4 ra[4], rb[4];

    #pragma unroll
    for (int i = 0; i < 4; i++) {
        ra[i] = *(const float4*)(Ap + (size_t)(32 * i) * CC);
        rb[i] = *(const float4*)(Bp + (size_t)(32 * i) * CC);
    }
    #pragma unroll
    for (int i = 0; i < 4; i++) {
        float* as = &As[0][lr + 32 * i][lc];
        as[0] = to_tf32(ra[i].x); as[1] = to_tf32(ra[i].y);
        as[2] = to_tf32(ra[i].z); as[3] = to_tf32(ra[i].w);
        float* bs = &Bs[0][lr + 32 * i][lc];
        bs[0] = to_tf32(rb[i].x); bs[1] = to_tf32(rb[i].y);
        bs[2] = to_tf32(rb[i].z); bs[3] = to_tf32(rb[i].w);
    }
    __syncthreads();

    for (int kt = 0; kt < CC / 16; kt++) {
        const int cur = kt & 1;
        const uint32_t aB = aBase + cur * BUFA;
        const uint32_t bB = bBase + cur * BUFA;

        if (kt + 1 < CC / 16) {
            const float* Ap2 = Ap + (kt + 1) * 16;
            const float* Bp2 = Bp + (kt + 1) * 16;
            #pragma unroll
            for (int i = 0; i < 4; i++) {
                ra[i] = *(const float4*)(Ap2 + (size_t)(32 * i) * CC);
                rb[i] = *(const float4*)(Bp2 + (size_t)(32 * i) * CC);
            }
        }

        #pragma unroll
        for (int kk = 0; kk < 2; kk++) {
            uint32_t a[4][4];
            #pragma unroll
            for (int i = 0; i < 4; i++)
                LDSM4(a[i], aB + i * 1280 + kk * 32);
            #pragma unroll
            for (int p = 0; p < 4; p++) {
                uint32_t b[4];
                LDSM4(b, bB + p * 1280 + kk * 32);
                #pragma unroll
                for (int i = 0; i < 4; i++) {
                    MMA_TF32(acc[i][2 * p],     a[i], b[0], b[1]);
                    MMA_TF32(acc[i][2 * p + 1], a[i], b[2], b[3]);
                }
            }
        }

        if (kt + 1 < CC / 16) {
            const int nxt = cur ^ 1;
            #pragma unroll
            for (int i = 0; i < 4; i++) {
                float* as = &As[nxt][lr + 32 * i][lc];
                as[0] = to_tf32(ra[i].x); as[1] = to_tf32(ra[i].y);
                as[2] = to_tf32(ra[i].z); as[3] = to_tf32(ra[i].w);
                float* bs = &Bs[nxt][lr + 32 * i][lc];
                bs[0] = to_tf32(rb[i].x); bs[1] = to_tf32(rb[i].y);
                bs[2] = to_tf32(rb[i].z); bs[3] = to_tf32(rb[i].w);
            }
        }
        __syncthreads();
    }
}

// ---------------------------------------------------------------------------
// Kernel 1: fused QKV projection. grid = (8, 64, 3), 128 threads.
// ---------------------------------------------------------------------------
__global__ void __launch_bounds__(128) qkv_kernel(const float* __restrict__ x,
                                                  const float* __restrict__ Wq,
                                                  const float* __restrict__ Wk,
                                                  const float* __restrict__ Wv)
{
    const int z = blockIdx.z;
    const float* W = (z == 0) ? Wq : (z == 1) ? Wk : Wv;
    float* dst     = (z == 0) ? g_Q : (z == 1) ? g_K : g_V;

    const int m0 = blockIdx.y * 128;
    const int n0 = blockIdx.x * 128;

    float acc[4][8][4];
    gemm_tf32(x, W, m0, n0, acc);

    const int lane = threadIdx.x & 31, wid = threadIdx.x >> 5;
    const int g = lane >> 2, ctid = lane & 3;
    const int wm = (wid & 1) * 64, wn = (wid >> 1) * 64;

    #pragma unroll
    for (int i = 0; i < 4; i++) {
        const int m = m0 + wm + 16 * i + g;
        const int b1 = m >> 11;
        const int t1 = m & (TT - 1);
        #pragma unroll
        for (int nt = 0; nt < 8; nt++) {
            const int n = n0 + wn + 8 * nt + 2 * ctid;
            const int h = n >> 6, d = n & 63;
            float* base = dst + ((size_t)(b1 * HH + h) * TT + t1) * DD + d;
            *(float2*)base            = make_float2(acc[i][nt][0], acc[i][nt][1]);
            *(float2*)(base + 8 * DD) = make_float2(acc[i][nt][2], acc[i][nt][3]);
        }
    }
}

// ---------------------------------------------------------------------------
// fast exp2 (FMA polynomial; inputs <= 0).
// ---------------------------------------------------------------------------
__device__ __forceinline__ float fexp2(float t)
{
    t = fmaxf(t, -126.0f);
    float r = t + 12582912.0f;
    int   n = __float_as_int(r) - 0x4B400000;
    float x = t - (r - 12582912.0f);
    float p = 1.33335581e-3f;
    p = fmaf(p, x, 9.61812910e-3f);
    p = fmaf(p, x, 5.55041087e-2f);
    p = fmaf(p, x, 2.40226507e-1f);
    p = fmaf(p, x, 6.93147182e-1f);
    p = fmaf(p, x, 1.0f);
    return p * __int_as_float((n + 127) << 23);
}

// Remap mma accumulator quad layout (cols 2c,2c+1; rows g,g+8) to
// m16n8k8 A-fragment layout (cols c,c+4; rows g,g+8) via intra-quad shfl.
// Inputs p0..p3 already tf32-rounded.
__device__ __forceinline__ void p_to_afrag(float p0, float p1, float p2, float p3,
                                           int lane, uint32_t a[4])
{
    const int base = lane & 28;
    const int c    = lane & 3;
    const int s0   = base | (c >> 1);
    const int s1   = s0 + 2;
    const float t00 = __shfl_sync(0xffffffffu, p0, s0);
    const float t01 = __shfl_sync(0xffffffffu, p1, s0);
    const float t10 = __shfl_sync(0xffffffffu, p2, s0);
    const float t11 = __shfl_sync(0xffffffffu, p3, s0);
    const float t20 = __shfl_sync(0xffffffffu, p0, s1);
    const float t21 = __shfl_sync(0xffffffffu, p1, s1);
    const float t30 = __shfl_sync(0xffffffffu, p2, s1);
    const float t31 = __shfl_sync(0xffffffffu, p3, s1);
    const bool odd = c & 1;
    a[0] = __float_as_uint(odd ? t01 : t00);   // row g,   col c
    a[1] = __float_as_uint(odd ? t11 : t10);   // row g+8, col c
    a[2] = __float_as_uint(odd ? t21 : t20);   // row g,   col c+4
    a[3] = __float_as_uint(odd ? t31 : t30);   // row g+8, col c+4
}

// ---------------------------------------------------------------------------
// Kernel 2: causal flash attention. grid = (8, 64), 256 threads (8 warps).
// 256 q-rows per block (32 rows/warp as two m16 tiles), 64-key tiles.
// P never touches smem: acc -> A-frag via quad shfl.
// ---------------------------------------------------------------------------
#define AP 68
#define ATTN_SMEM_BYTES ((256 + 64 + 64) * AP * 4)

__global__ void __launch_bounds__(256) attn_kernel()
{
    extern __shared__ float sm[];
    float* Qs = sm;                  // [256][AP]
    float* Ks = Qs + 256 * AP;       // [64][AP]
    float* Vt = Ks + 64 * AP;        // [64][AP]  V^T: [d][key]

    const int t    = threadIdx.x;
    const int lane = t & 31;
    const int wid  = t >> 5;             // 0..7, owns rows wid*32..wid*32+31
    const int g    = lane >> 2;
    const int ctid = lane & 3;
    const int bh   = blockIdx.y;
    const int qi   = gridDim.x - 1 - blockIdx.x;   // heavy tiles first
    const int t0   = qi * 256;
    const float scale = 0.125f;
    const float L2E   = 1.4426950408889634f;

    const float* Qg = g_Q + (size_t)bh * TT * DD;
    const float* Kg = g_K + (size_t)bh * TT * DD;
    const float* Vg = g_V + (size_t)bh * TT * DD;

    const int arow = (lane & 7) + ((lane >> 3) & 1) * 8;
    const int akw  = (lane >> 4) * 4;
    const int brow = (lane & 7) + (lane >> 4) * 8;
    const int bkw  = ((lane >> 3) & 1) * 4;

    const uint32_t aQ0 = smem_u32(Qs) + (((wid * 32 + arow) * AP + akw) << 2);
    const uint32_t aQ1 = aQ0 + (16 * AP << 2);
    const uint32_t bK  = smem_u32(Ks) + ((brow * AP + bkw) << 2);
    const uint32_t bV  = smem_u32(Vt) + ((brow * AP + bkw) << 2);
    const uint32_t PSTRIDE = 16 * AP * 4;

    // load Q tile (scaled, tf32): 256 rows x 64 cols
    #pragma unroll
    for (int it = 0; it < 16; it++) {
        int lin = it * 256 + t;
        int r = lin >> 4, c4 = (lin & 15) * 4;
        float4 v = *(const float4*)&Qg[(size_t)(t0 + r) * DD + c4];
        Qs[r * AP + c4 + 0] = to_tf32(v.x * scale);
        Qs[r * AP + c4 + 1] = to_tf32(v.y * scale);
        Qs[r * AP + c4 + 2] = to_tf32(v.z * scale);
        Qs[r * AP + c4 + 3] = to_tf32(v.w * scale);
    }

    float o[2][8][4];
    #pragma unroll
    for (int i = 0; i < 2; i++)
        #pragma unroll
        for (int nt = 0; nt < 8; nt++)
            #pragma unroll
            for (int c = 0; c < 4; c++) o[i][nt][c] = 0.f;
    float mr[2][2] = {{-1e30f, -1e30f}, {-1e30f, -1e30f}};
    float lr[2][2] = {{0.f, 0.f}, {0.f, 0.f}};

    const int wrow = t0 + wid * 32 + g;       // + i*16 (+8 for upper half)
    const int jmax = 4 * qi + 3;

    for (int j = 0; j <= jmax; j++) {
        __syncthreads();   // previous iter's K/Vt consumers done

        // stage K tile 64x64
        #pragma unroll
        for (int it = 0; it < 4; it++) {
            int lin = it * 256 + t;
            int r = lin >> 4, c4 = (lin & 15) * 4;
            float4 v = *(const float4*)&Kg[(size_t)(j * 64 + r) * DD + c4];
            Ks[r * AP + c4 + 0] = to_tf32(v.x);
            Ks[r * AP + c4 + 1] = to_tf32(v.y);
            Ks[r * AP + c4 + 2] = to_tf32(v.z);
            Ks[r * AP + c4 + 3] = to_tf32(v.w);
        }
        // stage V transposed: each thread one 4x4 block
        {
            const int kq = (t & 15) * 4;
            const int d4 = (t >> 4) * 4;
            float4 r0 = *(const float4*)&Vg[(size_t)(j * 64 + kq + 0) * DD + d4];
            float4 r1 = *(const float4*)&Vg[(size_t)(j * 64 + kq + 1) * DD + d4];
            float4 r2 = *(const float4*)&Vg[(size_t)(j * 64 + kq + 2) * DD + d4];
            float4 r3 = *(const float4*)&Vg[(size_t)(j * 64 + kq + 3) * DD + d4];
            *(float4*)&Vt[(d4 + 0) * AP + kq] =
                make_float4(to_tf32(r0.x), to_tf32(r1.x), to_tf32(r2.x), to_tf32(r3.x));
            *(float4*)&Vt[(d4 + 1) * AP + kq] =
                make_float4(to_tf32(r0.y), to_tf32(r1.y), to_tf32(r2.y), to_tf32(r3.y));
            *(float4*)&Vt[(d4 + 2) * AP + kq] =
                make_float4(to_tf32(r0.z), to_tf32(r1.z), to_tf32(r2.z), to_tf32(r3.z));
            *(float4*)&Vt[(d4 + 3) * AP + kq] =
                make_float4(to_tf32(r0.w), to_tf32(r1.w), to_tf32(r2.w), to_tf32(r3.w));
        }
        __syncthreads();

        // ---- S = Q * K^T : two m16 tiles x 64 keys ----
        float s[2][8][4];
        #pragma unroll
        for (int i = 0; i < 2; i++)
            #pragma unroll
            for (int nt = 0; nt < 8; nt++)
                #pragma unroll
                for (int c = 0; c < 4; c++) s[i][nt][c] = 0.f;

        #pragma unroll
        for (int kk = 0; kk < 8; kk++) {
            uint32_t a0[4], a1[4];
            LDSM4(a0, aQ0 + kk * 32);
            LDSM4(a1, aQ1 + kk * 32);
            #pragma unroll
            for (int p = 0; p < 4; p++) {
                uint32_t b[4];
                LDSM4(b, bK + p * PSTRIDE + kk * 32);
                MMA_TF32(s[0][2 * p],     a0, b[0], b[1]);
                MMA_TF32(s[0][2 * p + 1], a0, b[2], b[3]);
                MMA_TF32(s[1][2 * p],     a1, b[0], b[1]);
                MMA_TF32(s[1][2 * p + 1], a1, b[2], b[3]);
            }
        }

        // causal mask: only the last 4 k-tiles can cross the diagonal
        if (j >= 4 * qi) {
            const int kb = j * 64;
            #pragma unroll
            for (int i = 0; i < 2; i++) {
                const int rlo = wrow + 16 * i, rhi = rlo + 8;
                #pragma unroll
                for (int nt = 0; nt < 8; nt++) {
                    const int cg = kb + 8 * nt + 2 * ctid;
                    if (cg     > rlo) s[i][nt][0] = -1e30f;
                    if (cg + 1 > rlo) s[i][nt][1] = -1e30f;
                    if (cg     > rhi) s[i][nt][2] = -1e30f;
                    if (cg + 1 > rhi) s[i][nt][3] = -1e30f;
                }
            }
        }

        // ---- online softmax + PV per m-tile ----
        #pragma unroll
        for (int i = 0; i < 2; i++) {
            float mx0 = -1e30f, mx8 = -1e30f;
            #pragma unroll
            for (int nt = 0; nt < 8; nt++) {
                mx0 = fmaxf(mx0, fmaxf(s[i][nt][0], s[i][nt][1]));
                mx8 = fmaxf(mx8, fmaxf(s[i][nt][2], s[i][nt][3]));
            }
            mx0 = fmaxf(mx0, __shfl_xor_sync(0xffffffffu, mx0, 1));
            mx0 = fmaxf(mx0, __shfl_xor_sync(0xffffffffu, mx0, 2));
            mx8 = fmaxf(mx8, __shfl_xor_sync(0xffffffffu, mx8, 1));
            mx8 = fmaxf(mx8, __shfl_xor_sync(0xffffffffu, mx8, 2));

            const float mn0 = fmaxf(mr[i][0], mx0), mn8 = fmaxf(mr[i][1], mx8);
            const float f0 = fexp2((mr[i][0] - mn0) * L2E);
            const float f8 = fexp2((mr[i][1] - mn8) * L2E);
            mr[i][0] = mn0; mr[i][1] = mn8;

            #pragma unroll
            for (int nt = 0; nt < 8; nt++) {
                o[i][nt][0] *= f0; o[i][nt][1] *= f0;
                o[i][nt][2] *= f8; o[i][nt][3] *= f8;
            }

            float rs0 = 0.f, rs8 = 0.f;
            #pragma unroll
            for (int nt = 0; nt < 8; nt++) {
                const float p0 = fexp2((s[i][nt][0] - mn0) * L2E);
                const float p1 = fexp2((s[i][nt][1] - mn0) * L2E);
                const float p2 = fexp2((s[i][nt][2] - mn8) * L2E);
                const float p3 = fexp2((s[i][nt][3] - mn8) * L2E);
                rs0 += p0 + p1;
                rs8 += p2 + p3;
                s[i][nt][0] = to_tf32(p0);
                s[i][nt][1] = to_tf32(p1);
                s[i][nt][2] = to_tf32(p2);
                s[i][nt][3] = to_tf32(p3);
            }
            rs0 += __shfl_xor_sync(0xffffffffu, rs0, 1);
            rs0 += __shfl_xor_sync(0xffffffffu, rs0, 2);
            rs8 += __shfl_xor_sync(0xffffffffu, rs8, 1);
            rs8 += __shfl_xor_sync(0xffffffffu, rs8, 2);
            lr[i][0] = lr[i][0] * f0 + rs0;
            lr[i][1] = lr[i][1] * f8 + rs8;
        }

        // ---- O += P * V  (P from registers via quad shfl) ----
        #pragma unroll
        for (int kk = 0; kk < 8; kk++) {
            uint32_t pa0[4], pa1[4];
            p_to_afrag(s[0][kk][0], s[0][kk][1], s[0][kk][2], s[0][kk][3], lane, pa0);
            p_to_afrag(s[1][kk][0], s[1][kk][1], s[1][kk][2], s[1][kk][3], lane, pa1);
            #pragma unroll
            for (int p = 0; p < 4; p++) {
                uint32_t b[4];
                LDSM4(b, bV + p * PSTRIDE + kk * 32);
                MMA_TF32(o[0][2 * p],     pa0, b[0], b[1]);
                MMA_TF32(o[0][2 * p + 1], pa0, b[2], b[3]);
                MMA_TF32(o[1][2 * p],     pa1, b[0], b[1]);
                MMA_TF32(o[1][2 * p + 1], pa1, b[2], b[3]);
            }
        }
    }

    // epilogue: normalize + merge heads into g_Y [B,T,C]
    const int b1 = bh >> 4, h = bh & 15;
    #pragma unroll
    for (int i = 0; i < 2; i++) {
        const float li0 = 1.0f / lr[i][0], li8 = 1.0f / lr[i][1];
        const int r0 = wrow + 16 * i;
        float* y0 = g_Y + (size_t)(b1 * TT + r0) * CC + h * 64;
        float* y8 = y0 + (size_t)8 * CC;
        #pragma unroll
        for (int nt = 0; nt < 8; nt++) {
            *(float2*)&y0[8 * nt + 2 * ctid] =
                make_float2(o[i][nt][0] * li0, o[i][nt][1] * li0);
            *(float2*)&y8[8 * nt + 2 * ctid] =
                make_float2(o[i][nt][2] * li8, o[i][nt][3] * li8);
        }
    }
}

// ---------------------------------------------------------------------------
// Kernel 3: output projection  out = Y @ Wo^T + bo.  grid = (8, 64), 128 thr.
// ---------------------------------------------------------------------------
__global__ void __launch_bounds__(128) outproj_kernel(const float* __restrict__ Wo,
                                                      const float* __restrict__ bo,
                                                      float* __restrict__ out)
{
    const int m0 = blockIdx.y * 128;
    const int n0 = blockIdx.x * 128;

    float acc[4][8][4];
    gemm_tf32(g_Y, Wo, m0, n0, acc);

    const int lane = threadIdx.x & 31, wid = threadIdx.x >> 5;
    const int g = lane >> 2, ctid = lane & 3;
    const int wm = (wid & 1) * 64, wn = (wid >> 1) * 64;

    #pragma unroll
    for (int i = 0; i < 4; i++) {
        const int m = m0 + wm + 16 * i + g;
        #pragma unroll
        for (int nt = 0; nt < 8; nt++) {
            const int n = n0 + wn + 8 * nt + 2 * ctid;
            const float2 bias = *(const float2*)&bo[n];
            float* base = out + (size_t)m * CC + n;
            *(float2*)base = make_float2(acc[i][nt][0] + bias.x, acc[i][nt][1] + bias.y);
            *(float2*)(base + (size_t)8 * CC) =
                make_float2(acc[i][nt][2] + bias.x, acc[i][nt][3] + bias.y);
        }
    }
}

// ---------------------------------------------------------------------------
// Launch
// ---------------------------------------------------------------------------
extern "C" void kernel_launch(void* const* d_in, const int* in_sizes, int n_in,
                              void* d_out, int out_size)
{
    const float* x  = (const float*)d_in[0];
    const float* Wq = (const float*)d_in[1];
    const float* Wk = (const float*)d_in[2];
    const float* Wv = (const float*)d_in[3];
    const float* Wo = (const float*)d_in[4];
    const float* bo = (const float*)d_in[5];
    float* out = (float*)d_out;

    cudaFuncSetAttribute(attn_kernel, cudaFuncAttributeMaxDynamicSharedMemorySize,
                         ATTN_SMEM_BYTES);

    qkv_kernel<<<dim3(8, 64, 3), 128>>>(x, Wq, Wk, Wv);
    attn_kernel<<<dim3(8, 64), 256, ATTN_SMEM_BYTES>>>();
    outproj_kernel<<<dim3(8, 64), 128>>>(Wo, bo, out);
}

// round 9
// speedup vs baseline: 1.0726x; 1.0726x over previous
#include <cuda_runtime.h>
#include <cstdint>

// ---------------------------------------------------------------------------
// SABlock: causal MHA block. B=4, T=2048, C=1024, H=16, D=64.
// Round 9: attention rebuilt: V-key permutation kills PV shfl remap entirely
// (acc regs used directly as A-frag); K/V staging software-pipelined through
// registers with double-buffered smem (1 sync/iter, LDG latency hidden).
// GEMMs unchanged (round-6 mma.sync tf32).
// ---------------------------------------------------------------------------

#define BB 4
#define TT 2048
#define CC 1024
#define HH 16
#define DD 64

__device__ __align__(16) float g_Q[BB * HH * TT * DD];
__device__ __align__(16) float g_K[BB * HH * TT * DD];
__device__ __align__(16) float g_V[BB * HH * TT * DD];
__device__ __align__(16) float g_Y[BB * TT * CC];

__device__ __forceinline__ float to_tf32(float x) {
    uint32_t u;
    asm("cvt.rna.tf32.f32 %0, %1;" : "=r"(u) : "f"(x));
    return __uint_as_float(u);
}
__device__ __forceinline__ uint32_t tf32_bits(float x) {
    uint32_t u;
    asm("cvt.rna.tf32.f32 %0, %1;" : "=r"(u) : "f"(x));
    return u;
}
__device__ __forceinline__ uint32_t smem_u32(const void* p) {
    return (uint32_t)__cvta_generic_to_shared(p);
}

#define LDSM4(r, addr)                                                        \
    asm volatile("ldmatrix.sync.aligned.m8n8.x4.shared.b16 {%0,%1,%2,%3}, [%4];" \
                 : "=r"((r)[0]), "=r"((r)[1]), "=r"((r)[2]), "=r"((r)[3])     \
                 : "r"(addr))

#define MMA_TF32(c, a, b0_, b1_)                                              \
    asm volatile("mma.sync.aligned.m16n8k8.row.col.f32.tf32.tf32.f32 "        \
                 "{%0,%1,%2,%3},{%4,%5,%6,%7},{%8,%9},{%0,%1,%2,%3};"         \
                 : "+f"((c)[0]), "+f"((c)[1]), "+f"((c)[2]), "+f"((c)[3])     \
                 : "r"((a)[0]), "r"((a)[1]), "r"((a)[2]), "r"((a)[3]),        \
                   "r"(b0_), "r"(b1_))

// A-frag registers direct from S accumulator: order (c0, c2, c1, c3).
#define MMA_TF32_ACC_A(c, s0_, s1_, s2_, s3_, b0_, b1_)                       \
    asm volatile("mma.sync.aligned.m16n8k8.row.col.f32.tf32.tf32.f32 "        \
                 "{%0,%1,%2,%3},{%4,%5,%6,%7},{%8,%9},{%0,%1,%2,%3};"         \
                 : "+f"((c)[0]), "+f"((c)[1]), "+f"((c)[2]), "+f"((c)[3])     \
                 : "r"(s0_), "r"(s2_), "r"(s1_), "r"(s3_),                    \
                   "r"(b0_), "r"(b1_))

// ---------------------------------------------------------------------------
// tf32 GEMM core (unchanged): 128x128 block tile, 4 warps 64x64, K-step 16,
// double-buffered smem.
// ---------------------------------------------------------------------------
__device__ __forceinline__ void gemm_tf32(const float* __restrict__ A,
                                          const float* __restrict__ W,
                                          int m0, int n0, float acc[4][8][4])
{
    __shared__ float As[2][128][20];
    __shared__ float Bs[2][128][20];

    const int t    = threadIdx.x;
    const int lane = t & 31;
    const int wid  = t >> 5;
    const int wm   = (wid & 1) * 64;
    const int wn   = (wid >> 1) * 64;

    const int lr = t >> 2;
    const int lc = (t & 3) * 4;
    const float* Ap = A + (size_t)(m0 + lr) * CC + lc;
    const float* Bp = W + (size_t)(n0 + lr) * CC + lc;

    const int arow = (lane & 7) + ((lane >> 3) & 1) * 8;
    const int akw  = (lane >> 4) * 4;
    const int brow = (lane & 7) + (lane >> 4) * 8;
    const int bkw  = ((lane >> 3) & 1) * 4;

    const uint32_t aBase = smem_u32(&As[0][0][0]) + (((wm + arow) * 20 + akw) << 2);
    const uint32_t bBase = smem_u32(&Bs[0][0][0]) + (((wn + brow) * 20 + bkw) << 2);
    const uint32_t BUFA  = sizeof(float) * 128 * 20;

    #pragma unroll
    for (int i = 0; i < 4; i++)
        #pragma unroll
        for (int nt = 0; nt < 8; nt++)
            #pragma unroll
            for (int c = 0; c < 4; c++) acc[i][nt][c] = 0.f;

    float4 ra[4], rb[4];

    #pragma unroll
    for (int i = 0; i < 4; i++) {
        ra[i] = *(const float4*)(Ap + (size_t)(32 * i) * CC);
        rb[i] = *(const float4*)(Bp + (size_t)(32 * i) * CC);
    }
    #pragma unroll
    for (int i = 0; i < 4; i++) {
        float* as = &As[0][lr + 32 * i][lc];
        as[0] = to_tf32(ra[i].x); as[1] = to_tf32(ra[i].y);
        as[2] = to_tf32(ra[i].z); as[3] = to_tf32(ra[i].w);
        float* bs = &Bs[0][lr + 32 * i][lc];
        bs[0] = to_tf32(rb[i].x); bs[1] = to_tf32(rb[i].y);
        bs[2] = to_tf32(rb[i].z); bs[3] = to_tf32(rb[i].w);
    }
    __syncthreads();

    for (int kt = 0; kt < CC / 16; kt++) {
        const int cur = kt & 1;
        const uint32_t aB = aBase + cur * BUFA;
        const uint32_t bB = bBase + cur * BUFA;

        if (kt + 1 < CC / 16) {
            const float* Ap2 = Ap + (kt + 1) * 16;
            const float* Bp2 = Bp + (kt + 1) * 16;
            #pragma unroll
            for (int i = 0; i < 4; i++) {
                ra[i] = *(const float4*)(Ap2 + (size_t)(32 * i) * CC);
                rb[i] = *(const float4*)(Bp2 + (size_t)(32 * i) * CC);
            }
        }

        #pragma unroll
        for (int kk = 0; kk < 2; kk++) {
            uint32_t a[4][4];
            #pragma unroll
            for (int i = 0; i < 4; i++)
                LDSM4(a[i], aB + i * 1280 + kk * 32);
            #pragma unroll
            for (int p = 0; p < 4; p++) {
                uint32_t b[4];
                LDSM4(b, bB + p * 1280 + kk * 32);
                #pragma unroll
                for (int i = 0; i < 4; i++) {
                    MMA_TF32(acc[i][2 * p],     a[i], b[0], b[1]);
                    MMA_TF32(acc[i][2 * p + 1], a[i], b[2], b[3]);
                }
            }
        }

        if (kt + 1 < CC / 16) {
            const int nxt = cur ^ 1;
            #pragma unroll
            for (int i = 0; i < 4; i++) {
                float* as = &As[nxt][lr + 32 * i][lc];
                as[0] = to_tf32(ra[i].x); as[1] = to_tf32(ra[i].y);
                as[2] = to_tf32(ra[i].z); as[3] = to_tf32(ra[i].w);
                float* bs = &Bs[nxt][lr + 32 * i][lc];
                bs[0] = to_tf32(rb[i].x); bs[1] = to_tf32(rb[i].y);
                bs[2] = to_tf32(rb[i].z); bs[3] = to_tf32(rb[i].w);
            }
        }
        __syncthreads();
    }
}

// ---------------------------------------------------------------------------
// Kernel 1: fused QKV projection. grid = (8, 64, 3), 128 threads.
// ---------------------------------------------------------------------------
__global__ void __launch_bounds__(128) qkv_kernel(const float* __restrict__ x,
                                                  const float* __restrict__ Wq,
                                                  const float* __restrict__ Wk,
                                                  const float* __restrict__ Wv)
{
    const int z = blockIdx.z;
    const float* W = (z == 0) ? Wq : (z == 1) ? Wk : Wv;
    float* dst     = (z == 0) ? g_Q : (z == 1) ? g_K : g_V;

    const int m0 = blockIdx.y * 128;
    const int n0 = blockIdx.x * 128;

    float acc[4][8][4];
    gemm_tf32(x, W, m0, n0, acc);

    const int lane = threadIdx.x & 31, wid = threadIdx.x >> 5;
    const int g = lane >> 2, ctid = lane & 3;
    const int wm = (wid & 1) * 64, wn = (wid >> 1) * 64;

    #pragma unroll
    for (int i = 0; i < 4; i++) {
        const int m = m0 + wm + 16 * i + g;
        const int b1 = m >> 11;
        const int t1 = m & (TT - 1);
        #pragma unroll
        for (int nt = 0; nt < 8; nt++) {
            const int n = n0 + wn + 8 * nt + 2 * ctid;
            const int h = n >> 6, d = n & 63;
            float* base = dst + ((size_t)(b1 * HH + h) * TT + t1) * DD + d;
            *(float2*)base            = make_float2(acc[i][nt][0], acc[i][nt][1]);
            *(float2*)(base + 8 * DD) = make_float2(acc[i][nt][2], acc[i][nt][3]);
        }
    }
}

// ---------------------------------------------------------------------------
// fast exp2 (FMA polynomial; inputs <= 0).
// ---------------------------------------------------------------------------
__device__ __forceinline__ float fexp2(float t)
{
    t = fmaxf(t, -126.0f);
    float r = t + 12582912.0f;
    int   n = __float_as_int(r) - 0x4B400000;
    float x = t - (r - 12582912.0f);
    float p = 1.33335581e-3f;
    p = fmaf(p, x, 9.61812910e-3f);
    p = fmaf(p, x, 5.55041087e-2f);
    p = fmaf(p, x, 2.40226507e-1f);
    p = fmaf(p, x, 6.93147182e-1f);
    p = fmaf(p, x, 1.0f);
    return p * __int_as_float((n + 127) << 23);
}

// ---------------------------------------------------------------------------
// Kernel 2: causal flash attention. grid = (8, 64), 256 threads (8 warps).
// 256 q-rows per block, 64-key tiles, double-buffered K/Vt smem with
// register-pipelined staging (1 sync/iter). PV A-frags come straight from
// the S accumulator; V keys are pre-permuted within 8-groups to compensate.
// ---------------------------------------------------------------------------
#define AP 68
#define KVBUF (64 * AP)
#define ATTN_SMEM_BYTES ((256 * AP + 4 * KVBUF) * 4)

__global__ void __launch_bounds__(256) attn_kernel()
{
    extern __shared__ float sm[];
    float* Qs = sm;                   // [256][AP]
    float* Ks = Qs + 256 * AP;        // [2][64][AP]
    float* Vt = Ks + 2 * KVBUF;       // [2][64][AP]  V^T, keys permuted

    const int t    = threadIdx.x;
    const int lane = t & 31;
    const int wid  = t >> 5;
    const int g    = lane >> 2;
    const int ctid = lane & 3;
    const int bh   = blockIdx.y;
    const int qi   = gridDim.x - 1 - blockIdx.x;   // heavy tiles first
    const int t0   = qi * 256;
    const float scale = 0.125f;
    const float L2E   = 1.4426950408889634f;

    const float* Qg = g_Q + (size_t)bh * TT * DD;
    const float* Kg = g_K + (size_t)bh * TT * DD;
    const float* Vg = g_V + (size_t)bh * TT * DD;

    const int arow = (lane & 7) + ((lane >> 3) & 1) * 8;
    const int akw  = (lane >> 4) * 4;
    const int brow = (lane & 7) + (lane >> 4) * 8;
    const int bkw  = ((lane >> 3) & 1) * 4;

    const uint32_t aQ0 = smem_u32(Qs) + (((wid * 32 + arow) * AP + akw) << 2);
    const uint32_t aQ1 = aQ0 + (16 * AP << 2);
    const uint32_t bK  = smem_u32(Ks) + ((brow * AP + bkw) << 2);
    const uint32_t bV  = smem_u32(Vt) + ((brow * AP + bkw) << 2);
    const uint32_t PSTRIDE = 16 * AP * 4;
    const uint32_t BUFB    = KVBUF * 4;

    // staging index math
    const int kq = (t & 15) * 4;          // V: key base (4 rows)
    const int d4 = (t >> 4) * 4;          // V: d base (4 cols)
    // key permutation f^{-1} within 8-groups (compensates acc->A-frag reuse)
    const int vcolbase = kq & ~7;
    const int vo8      = kq & 7;          // 0 or 4

    // load Q tile (scaled, tf32): 256 rows x 64 cols
    #pragma unroll
    for (int it = 0; it < 16; it++) {
        int lin = it * 256 + t;
        int r = lin >> 4, c4 = (lin & 15) * 4;
        float4 v = *(const float4*)&Qg[(size_t)(t0 + r) * DD + c4];
        Qs[r * AP + c4 + 0] = to_tf32(v.x * scale);
        Qs[r * AP + c4 + 1] = to_tf32(v.y * scale);
        Qs[r * AP + c4 + 2] = to_tf32(v.z * scale);
        Qs[r * AP + c4 + 3] = to_tf32(v.w * scale);
    }

    float o[2][8][4];
    #pragma unroll
    for (int i = 0; i < 2; i++)
        #pragma unroll
        for (int nt = 0; nt < 8; nt++)
            #pragma unroll
            for (int c = 0; c < 4; c++) o[i][nt][c] = 0.f;
    float mr[2][2] = {{-1e30f, -1e30f}, {-1e30f, -1e30f}};
    float lrw[2][2] = {{0.f, 0.f}, {0.f, 0.f}};

    const int wrow = t0 + wid * 32 + g;
    const int jmax = 4 * qi + 3;

    float4 kreg[4], vreg[4];

    // ---- prologue: stage tile j=0 into buffer 0 ----
    #pragma unroll
    for (int it = 0; it < 4; it++) {
        int lin = it * 256 + t;
        int r = lin >> 4, c4 = (lin & 15) * 4;
        kreg[it] = *(const float4*)&Kg[(size_t)r * DD + c4];
    }
    #pragma unroll
    for (int i = 0; i < 4; i++)
        vreg[i] = *(const float4*)&Vg[(size_t)(kq + i) * DD + d4];

    {
        #pragma unroll
        for (int it = 0; it < 4; it++) {
            int lin = it * 256 + t;
            int r = lin >> 4, c4 = (lin & 15) * 4;
            float* ks = Ks + r * AP + c4;
            ks[0] = to_tf32(kreg[it].x); ks[1] = to_tf32(kreg[it].y);
            ks[2] = to_tf32(kreg[it].z); ks[3] = to_tf32(kreg[it].w);
        }
        const int P8[8] = {0, 4, 1, 5, 2, 6, 3, 7};
        #pragma unroll
        for (int i = 0; i < 4; i++) {
            const int col = vcolbase + P8[vo8 + i];
            float* vt = Vt + col;
            vt[(d4 + 0) * AP] = to_tf32(vreg[i].x);
            vt[(d4 + 1) * AP] = to_tf32(vreg[i].y);
            vt[(d4 + 2) * AP] = to_tf32(vreg[i].z);
            vt[(d4 + 3) * AP] = to_tf32(vreg[i].w);
        }
    }
    __syncthreads();

    for (int j = 0; j <= jmax; j++) {
        const int cur = j & 1;
        const uint32_t bKc = bK + cur * BUFB;
        const uint32_t bVc = bV + cur * BUFB;

        // issue next tile's loads (latency hidden behind compute)
        if (j < jmax) {
            const int kb = (j + 1) * 64;
            #pragma unroll
            for (int it = 0; it < 4; it++) {
                int lin = it * 256 + t;
                int r = lin >> 4, c4 = (lin & 15) * 4;
                kreg[it] = *(const float4*)&Kg[(size_t)(kb + r) * DD + c4];
            }
            #pragma unroll
            for (int i = 0; i < 4; i++)
                vreg[i] = *(const float4*)&Vg[(size_t)(kb + kq + i) * DD + d4];
        }

        // ---- S = Q * K^T : two m16 tiles x 64 keys ----
        float s[2][8][4];
        #pragma unroll
        for (int i = 0; i < 2; i++)
            #pragma unroll
            for (int nt = 0; nt < 8; nt++)
                #pragma unroll
                for (int c = 0; c < 4; c++) s[i][nt][c] = 0.f;

        #pragma unroll
        for (int kk = 0; kk < 8; kk++) {
            uint32_t a0[4], a1[4];
            LDSM4(a0, aQ0 + kk * 32);
            LDSM4(a1, aQ1 + kk * 32);
            #pragma unroll
            for (int p = 0; p < 4; p++) {
                uint32_t b[4];
                LDSM4(b, bKc + p * PSTRIDE + kk * 32);
                MMA_TF32(s[0][2 * p],     a0, b[0], b[1]);
                MMA_TF32(s[0][2 * p + 1], a0, b[2], b[3]);
                MMA_TF32(s[1][2 * p],     a1, b[0], b[1]);
                MMA_TF32(s[1][2 * p + 1], a1, b[2], b[3]);
            }
        }

        // causal mask: only the last 4 k-tiles can cross the diagonal
        if (j >= 4 * qi) {
            const int kb = j * 64;
            #pragma unroll
            for (int i = 0; i < 2; i++) {
                const int rlo = wrow + 16 * i, rhi = rlo + 8;
                #pragma unroll
                for (int nt = 0; nt < 8; nt++) {
                    const int cg = kb + 8 * nt + 2 * ctid;
                    if (cg     > rlo) s[i][nt][0] = -1e30f;
                    if (cg + 1 > rlo) s[i][nt][1] = -1e30f;
                    if (cg     > rhi) s[i][nt][2] = -1e30f;
                    if (cg + 1 > rhi) s[i][nt][3] = -1e30f;
                }
            }
        }

        // ---- online softmax (register-resident); P left in s[] as tf32 ----
        #pragma unroll
        for (int i = 0; i < 2; i++) {
            float mx0 = -1e30f, mx8 = -1e30f;
            #pragma unroll
            for (int nt = 0; nt < 8; nt++) {
                mx0 = fmaxf(mx0, fmaxf(s[i][nt][0], s[i][nt][1]));
                mx8 = fmaxf(mx8, fmaxf(s[i][nt][2], s[i][nt][3]));
            }
            mx0 = fmaxf(mx0, __shfl_xor_sync(0xffffffffu, mx0, 1));
            mx0 = fmaxf(mx0, __shfl_xor_sync(0xffffffffu, mx0, 2));
            mx8 = fmaxf(mx8, __shfl_xor_sync(0xffffffffu, mx8, 1));
            mx8 = fmaxf(mx8, __shfl_xor_sync(0xffffffffu, mx8, 2));

            const float mn0 = fmaxf(mr[i][0], mx0), mn8 = fmaxf(mr[i][1], mx8);
            const float f0 = fexp2((mr[i][0] - mn0) * L2E);
            const float f8 = fexp2((mr[i][1] - mn8) * L2E);
            mr[i][0] = mn0; mr[i][1] = mn8;

            #pragma unroll
            for (int nt = 0; nt < 8; nt++) {
                o[i][nt][0] *= f0; o[i][nt][1] *= f0;
                o[i][nt][2] *= f8; o[i][nt][3] *= f8;
            }

            float rs0 = 0.f, rs8 = 0.f;
            #pragma unroll
            for (int nt = 0; nt < 8; nt++) {
                const float p0 = fexp2((s[i][nt][0] - mn0) * L2E);
                const float p1 = fexp2((s[i][nt][1] - mn0) * L2E);
                const float p2 = fexp2((s[i][nt][2] - mn8) * L2E);
                const float p3 = fexp2((s[i][nt][3] - mn8) * L2E);
                rs0 += p0 + p1;
                rs8 += p2 + p3;
                s[i][nt][0] = to_tf32(p0);
                s[i][nt][1] = to_tf32(p1);
                s[i][nt][2] = to_tf32(p2);
                s[i][nt][3] = to_tf32(p3);
            }
            rs0 += __shfl_xor_sync(0xffffffffu, rs0, 1);
            rs0 += __shfl_xor_sync(0xffffffffu, rs0, 2);
            rs8 += __shfl_xor_sync(0xffffffffu, rs8, 1);
            rs8 += __shfl_xor_sync(0xffffffffu, rs8, 2);
            lrw[i][0] = lrw[i][0] * f0 + rs0;
            lrw[i][1] = lrw[i][1] * f8 + rs8;
        }

        // ---- O += P * V : acc regs ARE the A-frag (V keys pre-permuted) ----
        #pragma unroll
        for (int kk = 0; kk < 8; kk++) {
            #pragma unroll
            for (int p = 0; p < 4; p++) {
                uint32_t b[4];
                LDSM4(b, bVc + p * PSTRIDE + kk * 32);
                MMA_TF32_ACC_A(o[0][2 * p],
                               __float_as_uint(s[0][kk][0]), __float_as_uint(s[0][kk][1]),
                               __float_as_uint(s[0][kk][2]), __float_as_uint(s[0][kk][3]),
                               b[0], b[1]);
                MMA_TF32_ACC_A(o[0][2 * p + 1],
                               __float_as_uint(s[0][kk][0]), __float_as_uint(s[0][kk][1]),
                               __float_as_uint(s[0][kk][2]), __float_as_uint(s[0][kk][3]),
                               b[2], b[3]);
                MMA_TF32_ACC_A(o[1][2 * p],
                               __float_as_uint(s[1][kk][0]), __float_as_uint(s[1][kk][1]),
                               __float_as_uint(s[1][kk][2]), __float_as_uint(s[1][kk][3]),
                               b[0], b[1]);
                MMA_TF32_ACC_A(o[1][2 * p + 1],
                               __float_as_uint(s[1][kk][0]), __float_as_uint(s[1][kk][1]),
                               __float_as_uint(s[1][kk][2]), __float_as_uint(s[1][kk][3]),
                               b[2], b[3]);
            }
        }

        // ---- publish next tile into the other buffer ----
        if (j < jmax) {
            const int nb = cur ^ 1;
            float* Ksn = Ks + nb * KVBUF;
            float* Vtn = Vt + nb * KVBUF;
            #pragma unroll
            for (int it = 0; it < 4; it++) {
                int lin = it * 256 + t;
                int r = lin >> 4, c4 = (lin & 15) * 4;
                float* ks = Ksn + r * AP + c4;
                ks[0] = to_tf32(kreg[it].x); ks[1] = to_tf32(kreg[it].y);
                ks[2] = to_tf32(kreg[it].z); ks[3] = to_tf32(kreg[it].w);
            }
            const int P8[8] = {0, 4, 1, 5, 2, 6, 3, 7};
            #pragma unroll
            for (int i = 0; i < 4; i++) {
                const int col = vcolbase + P8[vo8 + i];
                float* vt = Vtn + col;
                vt[(d4 + 0) * AP] = to_tf32(vreg[i].x);
                vt[(d4 + 1) * AP] = to_tf32(vreg[i].y);
                vt[(d4 + 2) * AP] = to_tf32(vreg[i].z);
                vt[(d4 + 3) * AP] = to_tf32(vreg[i].w);
            }
        }
        __syncthreads();
    }

    // epilogue: normalize + merge heads into g_Y [B,T,C]
    const int b1 = bh >> 4, h = bh & 15;
    #pragma unroll
    for (int i = 0; i < 2; i++) {
        const float li0 = 1.0f / lrw[i][0], li8 = 1.0f / lrw[i][1];
        const int r0 = wrow + 16 * i;
        float* y0 = g_Y + (size_t)(b1 * TT + r0) * CC + h * 64;
        float* y8 = y0 + (size_t)8 * CC;
        #pragma unroll
        for (int nt = 0; nt < 8; nt++) {
            *(float2*)&y0[8 * nt + 2 * ctid] =
                make_float2(o[i][nt][0] * li0, o[i][nt][1] * li0);
            *(float2*)&y8[8 * nt + 2 * ctid] =
                make_float2(o[i][nt][2] * li8, o[i][nt][3] * li8);
        }
    }
}

// ---------------------------------------------------------------------------
// Kernel 3: output projection  out = Y @ Wo^T + bo.  grid = (8, 64), 128 thr.
// ---------------------------------------------------------------------------
__global__ void __launch_bounds__(128) outproj_kernel(const float* __restrict__ Wo,
                                                      const float* __restrict__ bo,
                                                      float* __restrict__ out)
{
    const int m0 = blockIdx.y * 128;
    const int n0 = blockIdx.x * 128;

    float acc[4][8][4];
    gemm_tf32(g_Y, Wo, m0, n0, acc);

    const int lane = threadIdx.x & 31, wid = threadIdx.x >> 5;
    const int g = lane >> 2, ctid = lane & 3;
    const int wm = (wid & 1) * 64, wn = (wid >> 1) * 64;

    #pragma unroll
    for (int i = 0; i < 4; i++) {
        const int m = m0 + wm + 16 * i + g;
        #pragma unroll
        for (int nt = 0; nt < 8; nt++) {
            const int n = n0 + wn + 8 * nt + 2 * ctid;
            const float2 bias = *(const float2*)&bo[n];
            float* base = out + (size_t)m * CC + n;
            *(float2*)base = make_float2(acc[i][nt][0] + bias.x, acc[i][nt][1] + bias.y);
            *(float2*)(base + (size_t)8 * CC) =
                make_float2(acc[i][nt][2] + bias.x, acc[i][nt][3] + bias.y);
        }
    }
}

// ---------------------------------------------------------------------------
// Launch
// ---------------------------------------------------------------------------
extern "C" void kernel_launch(void* const* d_in, const int* in_sizes, int n_in,
                              void* d_out, int out_size)
{
    const float* x  = (const float*)d_in[0];
    const float* Wq = (const float*)d_in[1];
    const float* Wk = (const float*)d_in[2];
    const float* Wv = (const float*)d_in[3];
    const float* Wo = (const float*)d_in[4];
    const float* bo = (const float*)d_in[5];
    float* out = (float*)d_out;

    cudaFuncSetAttribute(attn_kernel, cudaFuncAttributeMaxDynamicSharedMemorySize,
                         ATTN_SMEM_BYTES);

    qkv_kernel<<<dim3(8, 64, 3), 128>>>(x, Wq, Wk, Wv);
    attn_kernel<<<dim3(8, 64), 256, ATTN_SMEM_BYTES>>>();
    outproj_kernel<<<dim3(8, 64), 128>>>(Wo, bo, out);
}

// round 10
// speedup vs baseline: 1.0893x; 1.0156x over previous
#include <cuda_runtime.h>
#include <cstdint>

// ---------------------------------------------------------------------------
// SABlock: causal MHA block. B=4, T=2048, C=1024, H=16, D=64.
// Round 10: pre-rounded tf32 operands (one-time convert pass) + cp.async
// staging everywhere -> kills LDG/cvt/STS chain in GEMMs and attention.
// V staged with permuted-key loads + float4 stores.
// ---------------------------------------------------------------------------

#define BB 4
#define TT 2048
#define CC 1024
#define HH 16
#define DD 64

__device__ __align__(16) float g_X[BB * TT * CC];
__device__ __align__(16) float g_Wq[CC * CC];
__device__ __align__(16) float g_Wk[CC * CC];
__device__ __align__(16) float g_Wv[CC * CC];
__device__ __align__(16) float g_Wo[CC * CC];
__device__ __align__(16) float g_Q[BB * HH * TT * DD];
__device__ __align__(16) float g_K[BB * HH * TT * DD];
__device__ __align__(16) float g_V[BB * HH * TT * DD];
__device__ __align__(16) float g_Y[BB * TT * CC];

__device__ __forceinline__ float to_tf32(float x) {
    uint32_t u;
    asm("cvt.rna.tf32.f32 %0, %1;" : "=r"(u) : "f"(x));
    return __uint_as_float(u);
}
__device__ __forceinline__ uint32_t smem_u32(const void* p) {
    return (uint32_t)__cvta_generic_to_shared(p);
}

#define CPA16(dst, src)                                                       \
    asm volatile("cp.async.cg.shared.global [%0], [%1], 16;"                  \
                 :: "r"(dst), "l"(src) : "memory")
#define CPA_COMMIT() asm volatile("cp.async.commit_group;" ::: "memory")
#define CPA_WAIT0()  asm volatile("cp.async.wait_group 0;" ::: "memory")

#define LDSM4(r, addr)                                                        \
    asm volatile("ldmatrix.sync.aligned.m8n8.x4.shared.b16 {%0,%1,%2,%3}, [%4];" \
                 : "=r"((r)[0]), "=r"((r)[1]), "=r"((r)[2]), "=r"((r)[3])     \
                 : "r"(addr))

#define MMA_TF32(c, a, b0_, b1_)                                              \
    asm volatile("mma.sync.aligned.m16n8k8.row.col.f32.tf32.tf32.f32 "        \
                 "{%0,%1,%2,%3},{%4,%5,%6,%7},{%8,%9},{%0,%1,%2,%3};"         \
                 : "+f"((c)[0]), "+f"((c)[1]), "+f"((c)[2]), "+f"((c)[3])     \
                 : "r"((a)[0]), "r"((a)[1]), "r"((a)[2]), "r"((a)[3]),        \
                   "r"(b0_), "r"(b1_))

// A-frag direct from S accumulator: register order (c0, c2, c1, c3).
#define MMA_TF32_ACC_A(c, s0_, s1_, s2_, s3_, b0_, b1_)                       \
    asm volatile("mma.sync.aligned.m16n8k8.row.col.f32.tf32.tf32.f32 "        \
                 "{%0,%1,%2,%3},{%4,%5,%6,%7},{%8,%9},{%0,%1,%2,%3};"         \
                 : "+f"((c)[0]), "+f"((c)[1]), "+f"((c)[2]), "+f"((c)[3])     \
                 : "r"(s0_), "r"(s2_), "r"(s1_), "r"(s3_),                    \
                   "r"(b0_), "r"(b1_))

// ---------------------------------------------------------------------------
// Kernel 0: RNA-round fp32 -> tf32 bit pattern (grid-stride float4)
// ---------------------------------------------------------------------------
__global__ void round_kernel(const float* __restrict__ src,
                             float* __restrict__ dst, int n4)
{
    int i = blockIdx.x * blockDim.x + threadIdx.x;
    if (i < n4) {
        float4 v = ((const float4*)src)[i];
        ((float4*)dst)[i] = make_float4(to_tf32(v.x), to_tf32(v.y),
                                        to_tf32(v.z), to_tf32(v.w));
    }
}

// ---------------------------------------------------------------------------
// tf32 GEMM core, cp.async staging (operands pre-rounded).
// 128x128 block tile, 4 warps 64x64, K-step 16, double-buffered, 1 sync/kt.
// ---------------------------------------------------------------------------
__device__ __forceinline__ void gemm_tf32(const float* __restrict__ A,
                                          const float* __restrict__ W,
                                          int m0, int n0, float acc[4][8][4])
{
    __shared__ float As[2][128][20];
    __shared__ float Bs[2][128][20];

    const int t    = threadIdx.x;
    const int lane = t & 31;
    const int wid  = t >> 5;
    const int wm   = (wid & 1) * 64;
    const int wn   = (wid >> 1) * 64;

    const int lr = t >> 2;                  // 0..31
    const int lc = (t & 3) * 4;             // 0,4,8,12
    const float* Ap = A + (size_t)(m0 + lr) * CC + lc;
    const float* Bp = W + (size_t)(n0 + lr) * CC + lc;

    const uint32_t aSt = smem_u32(&As[0][0][0]) + lr * 80 + lc * 4;
    const uint32_t bSt = smem_u32(&Bs[0][0][0]) + lr * 80 + lc * 4;

    const int arow = (lane & 7) + ((lane >> 3) & 1) * 8;
    const int akw  = (lane >> 4) * 4;
    const int brow = (lane & 7) + (lane >> 4) * 8;
    const int bkw  = ((lane >> 3) & 1) * 4;

    const uint32_t aBase = smem_u32(&As[0][0][0]) + (((wm + arow) * 20 + akw) << 2);
    const uint32_t bBase = smem_u32(&Bs[0][0][0]) + (((wn + brow) * 20 + bkw) << 2);
    const uint32_t BUF   = 10240;           // 128*20*4

    #pragma unroll
    for (int i = 0; i < 4; i++)
        #pragma unroll
        for (int nt = 0; nt < 8; nt++)
            #pragma unroll
            for (int c = 0; c < 4; c++) acc[i][nt][c] = 0.f;

    // prologue: stage kt=0 into buffer 0
    #pragma unroll
    for (int i = 0; i < 4; i++) {
        CPA16(aSt + i * 2560, Ap + (size_t)(32 * i) * CC);
        CPA16(bSt + i * 2560, Bp + (size_t)(32 * i) * CC);
    }
    CPA_COMMIT();

    for (int kt = 0; kt < CC / 16; kt++) {
        const int cur = kt & 1;
        CPA_WAIT0();
        __syncthreads();

        if (kt + 1 < CC / 16) {
            const int nb = cur ^ 1;
            const float* Ap2 = Ap + (kt + 1) * 16;
            const float* Bp2 = Bp + (kt + 1) * 16;
            #pragma unroll
            for (int i = 0; i < 4; i++) {
                CPA16(aSt + nb * BUF + i * 2560, Ap2 + (size_t)(32 * i) * CC);
                CPA16(bSt + nb * BUF + i * 2560, Bp2 + (size_t)(32 * i) * CC);
            }
            CPA_COMMIT();
        }

        const uint32_t aB = aBase + cur * BUF;
        const uint32_t bB = bBase + cur * BUF;
        #pragma unroll
        for (int kk = 0; kk < 2; kk++) {
            uint32_t a[4][4];
            #pragma unroll
            for (int i = 0; i < 4; i++)
                LDSM4(a[i], aB + i * 1280 + kk * 32);
            #pragma unroll
            for (int p = 0; p < 4; p++) {
                uint32_t b[4];
                LDSM4(b, bB + p * 1280 + kk * 32);
                #pragma unroll
                for (int i = 0; i < 4; i++) {
                    MMA_TF32(acc[i][2 * p],     a[i], b[0], b[1]);
                    MMA_TF32(acc[i][2 * p + 1], a[i], b[2], b[3]);
                }
            }
        }
    }
}

// ---------------------------------------------------------------------------
// Kernel 1: fused QKV projection. grid = (8, 64, 3), 128 threads.
// Epilogue stores tf32-rounded (Q additionally pre-scaled by 1/8).
// ---------------------------------------------------------------------------
__global__ void __launch_bounds__(128) qkv_kernel()
{
    const int z = blockIdx.z;
    const float* W = (z == 0) ? g_Wq : (z == 1) ? g_Wk : g_Wv;
    float* dst     = (z == 0) ? g_Q : (z == 1) ? g_K : g_V;
    const float mul = (z == 0) ? 0.125f : 1.0f;

    const int m0 = blockIdx.y * 128;
    const int n0 = blockIdx.x * 128;

    float acc[4][8][4];
    gemm_tf32(g_X, W, m0, n0, acc);

    const int lane = threadIdx.x & 31, wid = threadIdx.x >> 5;
    const int g = lane >> 2, ctid = lane & 3;
    const int wm = (wid & 1) * 64, wn = (wid >> 1) * 64;

    #pragma unroll
    for (int i = 0; i < 4; i++) {
        const int m = m0 + wm + 16 * i + g;
        const int b1 = m >> 11;
        const int t1 = m & (TT - 1);
        #pragma unroll
        for (int nt = 0; nt < 8; nt++) {
            const int n = n0 + wn + 8 * nt + 2 * ctid;
            const int h = n >> 6, d = n & 63;
            float* base = dst + ((size_t)(b1 * HH + h) * TT + t1) * DD + d;
            *(float2*)base = make_float2(to_tf32(mul * acc[i][nt][0]),
                                         to_tf32(mul * acc[i][nt][1]));
            *(float2*)(base + 8 * DD) = make_float2(to_tf32(mul * acc[i][nt][2]),
                                                    to_tf32(mul * acc[i][nt][3]));
        }
    }
}

// ---------------------------------------------------------------------------
// fast exp2 (FMA polynomial; inputs <= 0).
// ---------------------------------------------------------------------------
__device__ __forceinline__ float fexp2(float t)
{
    t = fmaxf(t, -126.0f);
    float r = t + 12582912.0f;
    int   n = __float_as_int(r) - 0x4B400000;
    float x = t - (r - 12582912.0f);
    float p = 1.33335581e-3f;
    p = fmaf(p, x, 9.61812910e-3f);
    p = fmaf(p, x, 5.55041087e-2f);
    p = fmaf(p, x, 2.40226507e-1f);
    p = fmaf(p, x, 6.93147182e-1f);
    p = fmaf(p, x, 1.0f);
    return p * __int_as_float((n + 127) << 23);
}

// ---------------------------------------------------------------------------
// Kernel 2: causal flash attention. grid = (8, 64), 256 threads (8 warps).
// 256 q-rows/block, 64-key tiles, cp.async Q/K staging, permuted V staging
// with float4 stores, double-buffered K/Vt, 1 sync/iter.
// ---------------------------------------------------------------------------
#define AP 68
#define KVBUF (64 * AP)
#define ATTN_SMEM_BYTES ((256 * AP + 4 * KVBUF) * 4)

__global__ void __launch_bounds__(256) attn_kernel()
{
    extern __shared__ float sm[];
    float* Qs = sm;                   // [256][AP] (pre-scaled, pre-rounded)
    float* Ks = Qs + 256 * AP;        // [2][64][AP]
    float* Vt = Ks + 2 * KVBUF;       // [2][64][AP]  V^T, keys permuted

    const int t    = threadIdx.x;
    const int lane = t & 31;
    const int wid  = t >> 5;
    const int g    = lane >> 2;
    const int ctid = lane & 3;
    const int bh   = blockIdx.y;
    const int qi   = gridDim.x - 1 - blockIdx.x;   // heavy tiles first
    const int t0   = qi * 256;
    const float L2E = 1.4426950408889634f;

    const float* Qg = g_Q + (size_t)bh * TT * DD;
    const float* Kg = g_K + (size_t)bh * TT * DD;
    const float* Vg = g_V + (size_t)bh * TT * DD;

    const int arow = (lane & 7) + ((lane >> 3) & 1) * 8;
    const int akw  = (lane >> 4) * 4;
    const int brow = (lane & 7) + (lane >> 4) * 8;
    const int bkw  = ((lane >> 3) & 1) * 4;

    const uint32_t aQ0 = smem_u32(Qs) + (((wid * 32 + arow) * AP + akw) << 2);
    const uint32_t aQ1 = aQ0 + (16 * AP << 2);
    const uint32_t bK  = smem_u32(Ks) + ((brow * AP + bkw) << 2);
    const uint32_t bV  = smem_u32(Vt) + ((brow * AP + bkw) << 2);
    const uint32_t PSTRIDE = 16 * AP * 4;
    const uint32_t BUFB    = KVBUF * 4;

    // staging index math
    const int qr  = t >> 4;               // Q/K staging row lane base
    const int c16 = t & 15;               // 16B chunk index within row
    const uint32_t qDst = smem_u32(Qs) + qr * (AP * 4) + c16 * 16;
    const uint32_t kDst = smem_u32(Ks) + qr * (AP * 4) + c16 * 16;

    const int kq  = (t & 15) * 4;         // V: output col group base
    const int d4  = (t >> 4) * 4;         // V: d base (4 cols)
    const int vcb = kq & ~7;
    const int vo8 = kq & 7;               // 0 or 4
    const int koff = vo8 >> 2;            // 0 or 1

    // ---- prologue: Q (16 chunks/thread) + K0 (4 chunks/thread) ----
    #pragma unroll
    for (int it = 0; it < 16; it++) {
        const int r = qr + it * 16;
        CPA16(qDst + it * 16 * (AP * 4), Qg + (size_t)(t0 + r) * DD + c16 * 4);
    }
    #pragma unroll
    for (int it = 0; it < 4; it++) {
        const int r = qr + it * 16;
        CPA16(kDst + it * 16 * (AP * 4), Kg + (size_t)r * DD + c16 * 4);
    }
    CPA_COMMIT();

    float4 vreg[4];
    #pragma unroll
    for (int i = 0; i < 4; i++)
        vreg[i] = *(const float4*)&Vg[(size_t)(vcb + 2 * i + koff) * DD + d4];
    #pragma unroll
    for (int c = 0; c < 4; c++) {
        float4 w = make_float4(((const float*)&vreg[0])[c], ((const float*)&vreg[1])[c],
                               ((const float*)&vreg[2])[c], ((const float*)&vreg[3])[c]);
        *(float4*)&Vt[(d4 + c) * AP + vcb + vo8] = w;
    }
    CPA_WAIT0();
    __syncthreads();

    float o[2][8][4];
    #pragma unroll
    for (int i = 0; i < 2; i++)
        #pragma unroll
        for (int nt = 0; nt < 8; nt++)
            #pragma unroll
            for (int c = 0; c < 4; c++) o[i][nt][c] = 0.f;
    float mr[2][2] = {{-1e30f, -1e30f}, {-1e30f, -1e30f}};
    float lrw[2][2] = {{0.f, 0.f}, {0.f, 0.f}};

    const int wrow = t0 + wid * 32 + g;
    const int jmax = 4 * qi + 3;

    for (int j = 0; j <= jmax; j++) {
        const int cur = j & 1;
        const uint32_t bKc = bK + cur * BUFB;
        const uint32_t bVc = bV + cur * BUFB;

        // issue next tile: K via cp.async, V via LDG->regs
        if (j < jmax) {
            const int kb = (j + 1) * 64;
            const int nb = cur ^ 1;
            #pragma unroll
            for (int it = 0; it < 4; it++) {
                const int r = qr + it * 16;
                CPA16(kDst + nb * BUFB + it * 16 * (AP * 4),
                      Kg + (size_t)(kb + r) * DD + c16 * 4);
            }
            CPA_COMMIT();
            #pragma unroll
            for (int i = 0; i < 4; i++)
                vreg[i] = *(const float4*)&Vg[(size_t)(kb + vcb + 2 * i + koff) * DD + d4];
        }

        // ---- S = Q * K^T ----
        float s[2][8][4];
        #pragma unroll
        for (int i = 0; i < 2; i++)
            #pragma unroll
            for (int nt = 0; nt < 8; nt++)
                #pragma unroll
                for (int c = 0; c < 4; c++) s[i][nt][c] = 0.f;

        #pragma unroll
        for (int kk = 0; kk < 8; kk++) {
            uint32_t a0[4], a1[4];
            LDSM4(a0, aQ0 + kk * 32);
            LDSM4(a1, aQ1 + kk * 32);
            #pragma unroll
            for (int p = 0; p < 4; p++) {
                uint32_t b[4];
                LDSM4(b, bKc + p * PSTRIDE + kk * 32);
                MMA_TF32(s[0][2 * p],     a0, b[0], b[1]);
                MMA_TF32(s[0][2 * p + 1], a0, b[2], b[3]);
                MMA_TF32(s[1][2 * p],     a1, b[0], b[1]);
                MMA_TF32(s[1][2 * p + 1], a1, b[2], b[3]);
            }
        }

        // causal mask
        if (j >= 4 * qi) {
            const int kb = j * 64;
            #pragma unroll
            for (int i = 0; i < 2; i++) {
                const int rlo = wrow + 16 * i, rhi = rlo + 8;
                #pragma unroll
                for (int nt = 0; nt < 8; nt++) {
                    const int cg = kb + 8 * nt + 2 * ctid;
                    if (cg     > rlo) s[i][nt][0] = -1e30f;
                    if (cg + 1 > rlo) s[i][nt][1] = -1e30f;
                    if (cg     > rhi) s[i][nt][2] = -1e30f;
                    if (cg + 1 > rhi) s[i][nt][3] = -1e30f;
                }
            }
        }

        // ---- online softmax (register-resident); P left in s[] as tf32 ----
        #pragma unroll
        for (int i = 0; i < 2; i++) {
            float mx0 = -1e30f, mx8 = -1e30f;
            #pragma unroll
            for (int nt = 0; nt < 8; nt++) {
                mx0 = fmaxf(mx0, fmaxf(s[i][nt][0], s[i][nt][1]));
                mx8 = fmaxf(mx8, fmaxf(s[i][nt][2], s[i][nt][3]));
            }
            mx0 = fmaxf(mx0, __shfl_xor_sync(0xffffffffu, mx0, 1));
            mx0 = fmaxf(mx0, __shfl_xor_sync(0xffffffffu, mx0, 2));
            mx8 = fmaxf(mx8, __shfl_xor_sync(0xffffffffu, mx8, 1));
            mx8 = fmaxf(mx8, __shfl_xor_sync(0xffffffffu, mx8, 2));

            const float mn0 = fmaxf(mr[i][0], mx0), mn8 = fmaxf(mr[i][1], mx8);
            const float f0 = fexp2((mr[i][0] - mn0) * L2E);
            const float f8 = fexp2((mr[i][1] - mn8) * L2E);
            mr[i][0] = mn0; mr[i][1] = mn8;

            #pragma unroll
            for (int nt = 0; nt < 8; nt++) {
                o[i][nt][0] *= f0; o[i][nt][1] *= f0;
                o[i][nt][2] *= f8; o[i][nt][3] *= f8;
            }

            float rs0 = 0.f, rs8 = 0.f;
            #pragma unroll
            for (int nt = 0; nt < 8; nt++) {
                const float p0 = fexp2((s[i][nt][0] - mn0) * L2E);
                const float p1 = fexp2((s[i][nt][1] - mn0) * L2E);
                const float p2 = fexp2((s[i][nt][2] - mn8) * L2E);
                const float p3 = fexp2((s[i][nt][3] - mn8) * L2E);
                rs0 += p0 + p1;
                rs8 += p2 + p3;
                s[i][nt][0] = to_tf32(p0);
                s[i][nt][1] = to_tf32(p1);
                s[i][nt][2] = to_tf32(p2);
                s[i][nt][3] = to_tf32(p3);
            }
            rs0 += __shfl_xor_sync(0xffffffffu, rs0, 1);
            rs0 += __shfl_xor_sync(0xffffffffu, rs0, 2);
            rs8 += __shfl_xor_sync(0xffffffffu, rs8, 1);
            rs8 += __shfl_xor_sync(0xffffffffu, rs8, 2);
            lrw[i][0] = lrw[i][0] * f0 + rs0;
            lrw[i][1] = lrw[i][1] * f8 + rs8;
        }

        // ---- O += P * V : acc regs ARE the A-frag (V keys pre-permuted) ----
        #pragma unroll
        for (int kk = 0; kk < 8; kk++) {
            #pragma unroll
            for (int p = 0; p < 4; p++) {
                uint32_t b[4];
                LDSM4(b, bVc + p * PSTRIDE + kk * 32);
                MMA_TF32_ACC_A(o[0][2 * p],
                               __float_as_uint(s[0][kk][0]), __float_as_uint(s[0][kk][1]),
                               __float_as_uint(s[0][kk][2]), __float_as_uint(s[0][kk][3]),
                               b[0], b[1]);
                MMA_TF32_ACC_A(o[0][2 * p + 1],
                               __float_as_uint(s[0][kk][0]), __float_as_uint(s[0][kk][1]),
                               __float_as_uint(s[0][kk][2]), __float_as_uint(s[0][kk][3]),
                               b[2], b[3]);
                MMA_TF32_ACC_A(o[1][2 * p],
                               __float_as_uint(s[1][kk][0]), __float_as_uint(s[1][kk][1]),
                               __float_as_uint(s[1][kk][2]), __float_as_uint(s[1][kk][3]),
                               b[0], b[1]);
                MMA_TF32_ACC_A(o[1][2 * p + 1],
                               __float_as_uint(s[1][kk][0]), __float_as_uint(s[1][kk][1]),
                               __float_as_uint(s[1][kk][2]), __float_as_uint(s[1][kk][3]),
                               b[2], b[3]);
            }
        }

        // ---- publish next V tile; wait for next K tile ----
        if (j < jmax) {
            const int nb = cur ^ 1;
            float* Vtn = Vt + nb * KVBUF;
            #pragma unroll
            for (int c = 0; c < 4; c++) {
                float4 w = make_float4(((const float*)&vreg[0])[c],
                                       ((const float*)&vreg[1])[c],
                                       ((const float*)&vreg[2])[c],
                                       ((const float*)&vreg[3])[c]);
                *(float4*)&Vtn[(d4 + c) * AP + vcb + vo8] = w;
            }
            CPA_WAIT0();
        }
        __syncthreads();
    }

    // epilogue: normalize + round + merge heads into g_Y [B,T,C]
    const int b1 = bh >> 4, h = bh & 15;
    #pragma unroll
    for (int i = 0; i < 2; i++) {
        const float li0 = 1.0f / lrw[i][0], li8 = 1.0f / lrw[i][1];
        const int r0 = wrow + 16 * i;
        float* y0 = g_Y + (size_t)(b1 * TT + r0) * CC + h * 64;
        float* y8 = y0 + (size_t)8 * CC;
        #pragma unroll
        for (int nt = 0; nt < 8; nt++) {
            *(float2*)&y0[8 * nt + 2 * ctid] =
                make_float2(to_tf32(o[i][nt][0] * li0), to_tf32(o[i][nt][1] * li0));
            *(float2*)&y8[8 * nt + 2 * ctid] =
                make_float2(to_tf32(o[i][nt][2] * li8), to_tf32(o[i][nt][3] * li8));
        }
    }
}

// ---------------------------------------------------------------------------
// Kernel 3: output projection  out = Y @ Wo^T + bo.  grid = (8, 64), 128 thr.
// ---------------------------------------------------------------------------
__global__ void __launch_bounds__(128) outproj_kernel(const float* __restrict__ bo,
                                                      float* __restrict__ out)
{
    const int m0 = blockIdx.y * 128;
    const int n0 = blockIdx.x * 128;

    float acc[4][8][4];
    gemm_tf32(g_Y, g_Wo, m0, n0, acc);

    const int lane = threadIdx.x & 31, wid = threadIdx.x >> 5;
    const int g = lane >> 2, ctid = lane & 3;
    const int wm = (wid & 1) * 64, wn = (wid >> 1) * 64;

    #pragma unroll
    for (int i = 0; i < 4; i++) {
        const int m = m0 + wm + 16 * i + g;
        #pragma unroll
        for (int nt = 0; nt < 8; nt++) {
            const int n = n0 + wn + 8 * nt + 2 * ctid;
            const float2 bias = *(const float2*)&bo[n];
            float* base = out + (size_t)m * CC + n;
            *(float2*)base = make_float2(acc[i][nt][0] + bias.x, acc[i][nt][1] + bias.y);
            *(float2*)(base + (size_t)8 * CC) =
                make_float2(acc[i][nt][2] + bias.x, acc[i][nt][3] + bias.y);
        }
    }
}

// ---------------------------------------------------------------------------
// Launch
// ---------------------------------------------------------------------------
extern "C" void kernel_launch(void* const* d_in, const int* in_sizes, int n_in,
                              void* d_out, int out_size)
{
    const float* x  = (const float*)d_in[0];
    const float* Wq = (const float*)d_in[1];
    const float* Wk = (const float*)d_in[2];
    const float* Wv = (const float*)d_in[3];
    const float* Wo = (const float*)d_in[4];
    const float* bo = (const float*)d_in[5];
    float* out = (float*)d_out;

    cudaFuncSetAttribute(attn_kernel, cudaFuncAttributeMaxDynamicSharedMemorySize,
                         ATTN_SMEM_BYTES);

    float* gX;  cudaGetSymbolAddress((void**)&gX,  g_X);
    float* gWq; cudaGetSymbolAddress((void**)&gWq, g_Wq);
    float* gWk; cudaGetSymbolAddress((void**)&gWk, g_Wk);
    float* gWv; cudaGetSymbolAddress((void**)&gWv, g_Wv);
    float* gWo; cudaGetSymbolAddress((void**)&gWo, g_Wo);

    const int nX4 = BB * TT * CC / 4;   // 2,097,152
    const int nW4 = CC * CC / 4;        // 262,144
    round_kernel<<<(nX4 + 255) / 256, 256>>>(x,  gX,  nX4);
    round_kernel<<<(nW4 + 255) / 256, 256>>>(Wq, gWq, nW4);
    round_kernel<<<(nW4 + 255) / 256, 256>>>(Wk, gWk, nW4);
    round_kernel<<<(nW4 + 255) / 256, 256>>>(Wv, gWv, nW4);
    round_kernel<<<(nW4 + 255) / 256, 256>>>(Wo, gWo, nW4);

    qkv_kernel<<<dim3(8, 64, 3), 128>>>();
    attn_kernel<<<dim3(8, 64), 256, ATTN_SMEM_BYTES>>>();
    outproj_kernel<<<dim3(8, 64), 128>>>(bo, out);
}